// round 16
// baseline (speedup 1.0000x reference)
#include <cuda_runtime.h>
#include <cstdint>

// Shapes (fixed by the problem)
#define D_MODEL   1024
#define HEAD_DIM  64
#define NUM_HEADS 16
#define BATCH     8
#define SEQ       4096
#define KSLICES   16          // K-split for the V GEMV (phase 1)

#define NPROLOG   128         // prologue CTAs (one per SM, all co-resident)
#define WO_PER_THREAD (HEAD_DIM / 2)   // 32 Wo values prefetched per thread

// Scratch + sync (allocation-free rule: __device__ globals).
// Data buffers fully overwritten each replay; counters reset by last arriver.
__device__ float g_Vpart[KSLICES * BATCH * HEAD_DIM];
__device__ float g_row[BATCH * D_MODEL];
__device__ int   g_cnt1 = 0;   // phase-1 arrivals (target NPROLOG)
__device__ int   g_cnt2 = 0;   // phase-2 arrivals (target NPROLOG)

// ---------------------------------------------------------------------------
// Kernel 1 (fused prologue), grid = 128 CTAs x 256 threads:
//  Entry  : issue 32 independent Wo loads into registers (no dependence on
//           phase 1 / the gate -> their DRAM latency overlaps both).
//  Phase 1: g_Vpart[ks][b][d] = sum_{i in slice} value[b,i]*Wv[i,d]
//           + distributed g_row[b,j] = bo[j] reset.
//  Gate   : counter barrier across the 128 CTAs (one per SM -> co-resident).
//  Phase 2: pure register FMAs against prefetched Wo, then atomicAdd.
//  Signals griddepcontrol.launch_dependents right after its atomics.
// ---------------------------------------------------------------------------
__global__ __launch_bounds__(256, 1)
void prologue_fused_kernel(const float* __restrict__ value,
                           const float* __restrict__ Wv,
                           const float* __restrict__ bv,
                           const float* __restrict__ Wo,
                           const float* __restrict__ bo) {
    const int bid = blockIdx.x;           // 0..127
    const int t   = threadIdx.x;          // 0..255

    __shared__ float red[4][HEAD_DIM];
    __shared__ float sV[BATCH * HEAD_DIM];

    // ---- Wo register prefetch (issued first; arrives during phase1+gate) --
    const int j    = (bid & 3) * 256 + t;           // 0..1023
    const int h    = (bid >> 2) & (NUM_HEADS - 1);  // 0..15
    const int half = bid >> 6;                      // 0..1 -> ii split
    const int ii0  = half * WO_PER_THREAD;

    float wreg[WO_PER_THREAD];
    {
        const float* wcol = Wo + ((size_t)h * HEAD_DIM + ii0) * D_MODEL + j;
        #pragma unroll
        for (int ii = 0; ii < WO_PER_THREAD; ++ii)
            wreg[ii] = __ldg(wcol + (size_t)ii * D_MODEL);   // coalesced
    }

    // ---- Phase 1 ---------------------------------------------------------
    // g_row reset: 128*256 = 32768 threads cover 8192 elements.
    const int gid = bid * 256 + t;
    if (gid < BATCH * D_MODEL)
        g_row[gid] = bo[gid & (D_MODEL - 1)];

    {
        const int ks  = bid & (KSLICES - 1);   // 0..15
        const int b   = bid >> 4;              // 0..7
        const int d   = t & (HEAD_DIM - 1);    // 0..63
        const int sub = t >> 6;                // 0..3
        const int i0  = ks * (D_MODEL / KSLICES) + sub * (D_MODEL / KSLICES / 4);
        const float* vrow = value + b * D_MODEL;

        float acc = 0.f;
        #pragma unroll
        for (int i = 0; i < D_MODEL / KSLICES / 4; ++i) {   // 16 iters
            const int ii = i0 + i;
            acc += vrow[ii] * Wv[ii * HEAD_DIM + d];
        }
        red[sub][d] = acc;
        __syncthreads();
        if (sub == 0) {
            g_Vpart[(ks * BATCH + b) * HEAD_DIM + d] =
                red[0][d] + red[1][d] + red[2][d] + red[3][d];
        }
    }
    __syncthreads();
    if (t == 0) { __threadfence(); atomicAdd(&g_cnt1, 1); }

    // ---- Gate (128 CTAs, one per SM -> cannot deadlock) ------------------
    if (t == 0) {
        volatile int* p = &g_cnt1;
        while (*p < NPROLOG) __nanosleep(64);
        __threadfence();
    }
    __syncthreads();

    // ---- Phase 2: fold V partials, FMA against prefetched Wo -------------
    {
        #pragma unroll
        for (int e = t; e < BATCH * HEAD_DIM; e += 256) {
            const int d2 = e & (HEAD_DIM - 1);
            float s = bv[d2];
            #pragma unroll
            for (int kk = 0; kk < KSLICES; ++kk)
                s += g_Vpart[kk * BATCH * HEAD_DIM + e];
            sV[e] = s;
        }
        __syncthreads();

        float accb[BATCH];
        #pragma unroll
        for (int b2 = 0; b2 < BATCH; ++b2) accb[b2] = 0.f;

        #pragma unroll
        for (int ii = 0; ii < WO_PER_THREAD; ++ii) {
            const float w = wreg[ii];
            const float* vv = sV + ii0 + ii;
            #pragma unroll
            for (int b2 = 0; b2 < BATCH; ++b2)
                accb[b2] += vv[b2 * HEAD_DIM] * w;      // smem broadcast
        }
        #pragma unroll
        for (int b2 = 0; b2 < BATCH; ++b2)
            atomicAdd(&g_row[b2 * D_MODEL + j], accb[b2]);
    }

    // ---- Release the broadcast as soon as this CTA's work is globally
    //      visible (all NPROLOG CTAs must signal before dependents' wait
    //      unblocks -> g_row is complete at that point).
    __threadfence();
    asm volatile("griddepcontrol.launch_dependents;" ::: "memory");

    // ---- Counter reset for next replay (last arriver) --------------------
    __syncthreads();
    if (t == 0) {
        if (atomicAdd(&g_cnt2, 1) == NPROLOG - 1) {
            g_cnt1 = 0;
            __threadfence();
            g_cnt2 = 0;
        }
    }
}

// ---------------------------------------------------------------------------
// Kernel 2: out[b,s,:] = row[b,:]. 134 MB of float4 stores; measured at the
// LTS store-path cap (~6 TB/s effective -> ~21-22 us floor). PDL-launched so
// its 1024-CTA ramp overlaps the prologue.
// ---------------------------------------------------------------------------
#define S_PER_BLOCK 32
#define ROW_VEC4    (D_MODEL / 4)   // 256

__global__ __launch_bounds__(256, 8)
void broadcast_kernel(float4* __restrict__ out) {
    const int b  = blockIdx.y;
    const int s0 = blockIdx.x * S_PER_BLOCK;
    const int t  = threadIdx.x;

    // Block until the prologue grid has made g_row visible.
    asm volatile("griddepcontrol.wait;" ::: "memory");

    const float4 v = reinterpret_cast<const float4*>(g_row)[b * ROW_VEC4 + t];

    size_t base = ((size_t)b * SEQ + s0) * ROW_VEC4 + t;
    #pragma unroll
    for (int s = 0; s < S_PER_BLOCK; ++s) {
        out[base + (size_t)s * ROW_VEC4] = v;
    }
}

// ---------------------------------------------------------------------------
// Inputs (metadata order): 0 query, 1 key, 2 value, 3 Wq, 4 bq,
//                          5 Wk, 6 bk, 7 Wv, 8 bv, 9 Wo, 10 bo
// softmax over kv_len=1 is identically 1 -> query/key/Wq/bq/Wk/bk are dead.
// ---------------------------------------------------------------------------
extern "C" void kernel_launch(void* const* d_in, const int* in_sizes, int n_in,
                              void* d_out, int out_size) {
    const float* value = (const float*)d_in[2];
    const float* Wv    = (const float*)d_in[7];
    const float* bv    = (const float*)d_in[8];
    const float* Wo    = (const float*)d_in[9];
    const float* bo    = (const float*)d_in[10];
    float* out = (float*)d_out;

    prologue_fused_kernel<<<NPROLOG, 256>>>(value, Wv, bv, Wo, bo);

    // Broadcast launched as a programmatic dependent: spins up during the
    // prologue, blocks at griddepcontrol.wait until g_row is ready.
    cudaLaunchConfig_t cfg = {};
    cfg.gridDim  = dim3(SEQ / S_PER_BLOCK, BATCH);
    cfg.blockDim = dim3(256);
    cfg.stream   = 0;
    cudaLaunchAttribute attr[1];
    attr[0].id = cudaLaunchAttributeProgrammaticStreamSerialization;
    attr[0].val.programmaticStreamSerializationAllowed = 1;
    cfg.attrs = attr;
    cfg.numAttrs = 1;
    float4* out4 = (float4*)out;
    cudaLaunchKernelEx(&cfg, broadcast_kernel, out4);
}

// round 17
// speedup vs baseline: 1.0212x; 1.0212x over previous
#include <cuda_runtime.h>
#include <cstdint>

// Shapes (fixed by the problem)
#define D_MODEL   1024
#define HEAD_DIM  64
#define NUM_HEADS 16
#define BATCH     8
#define SEQ       4096
#define KSLICES   8           // K-split for the V GEMV (phase 1)

#define NPROLOG   128         // prologue CTAs (one per SM, all co-resident)
#define WO_PER_THREAD (HEAD_DIM / 2)   // 32 Wo values per thread (half split)

// Scratch + sync (allocation-free rule: __device__ globals).
// Data buffers fully overwritten each replay; counters reset by last arriver.
__device__ float g_Vpart[KSLICES * BATCH * HEAD_DIM];
__device__ float g_row[BATCH * D_MODEL];
__device__ int   g_cnt1 = 0;   // phase-1 arrivals (target NPROLOG)
__device__ int   g_cnt2 = 0;   // phase-2 arrivals (target NPROLOG)

// ---------------------------------------------------------------------------
// Kernel 1 (fused prologue), grid = 128 CTAs x 256 threads:
//  Phase 1 : (64 CTAs) V partials, 32 loads/thread + g_row = bo reset.
//  Prefetch: AFTER phase-1 loads are in flight, each thread cp.async's its
//            32 Wo values into smem (no registers held; latency drains
//            during the reduction + gate spin).
//  Gate    : counter barrier (128 CTAs, one per SM -> co-resident).
//  Phase 2 : fold V partials (8 slices), FMA against smem Wo, atomicAdd.
//  Signals griddepcontrol.launch_dependents once g_row is visible.
// ---------------------------------------------------------------------------
__global__ __launch_bounds__(256, 1)
void prologue_fused_kernel(const float* __restrict__ value,
                           const float* __restrict__ Wv,
                           const float* __restrict__ bv,
                           const float* __restrict__ Wo,
                           const float* __restrict__ bo) {
    const int bid = blockIdx.x;           // 0..127
    const int t   = threadIdx.x;          // 0..255

    __shared__ float red[4][HEAD_DIM];                  // 1 KB
    __shared__ float sV[BATCH * HEAD_DIM];              // 2 KB
    __shared__ float swo[WO_PER_THREAD * 256];          // 32 KB

    const int j    = (bid & 3) * 256 + t;           // 0..1023
    const int h    = (bid >> 2) & (NUM_HEADS - 1);  // 0..15
    const int half = bid >> 6;                      // 0..1 -> ii split
    const int ii0  = half * WO_PER_THREAD;

    // ---- g_row reset (first 32 CTAs cover the 8192 elements) -------------
    const int gid = bid * 256 + t;
    if (gid < BATCH * D_MODEL)
        g_row[gid] = bo[gid & (D_MODEL - 1)];

    // ---- Phase 1: V partials (first 64 CTAs; loads issue FIRST) ----------
    float acc = 0.f;
    int d = t & (HEAD_DIM - 1), sub = t >> 6;
    if (bid < KSLICES * BATCH) {
        const int ks = bid & (KSLICES - 1);    // 0..7
        const int b  = bid >> 3;               // 0..7
        const int i0 = ks * (D_MODEL / KSLICES) + sub * (D_MODEL / KSLICES / 4);
        const float* vrow = value + b * D_MODEL;
        #pragma unroll
        for (int i = 0; i < D_MODEL / KSLICES / 4; ++i) {   // 32 iters
            const int ii = i0 + i;
            acc += vrow[ii] * Wv[ii * HEAD_DIM + d];
        }
    }

    // ---- Wo smem prefetch (issues AFTER phase-1 loads; no regs held) -----
    {
        const uint32_t sbase = (uint32_t)__cvta_generic_to_shared(swo);
        const float* wcol = Wo + ((size_t)h * HEAD_DIM + ii0) * D_MODEL + j;
        #pragma unroll
        for (int ii = 0; ii < WO_PER_THREAD; ++ii) {
            asm volatile("cp.async.ca.shared.global [%0], [%1], 4;"
                         :: "r"(sbase + (uint32_t)((ii * 256 + t) * 4)),
                            "l"(wcol + (size_t)ii * D_MODEL)
                         : "memory");
        }
        asm volatile("cp.async.commit_group;" ::: "memory");
    }

    // ---- Phase-1 reduction + publish -------------------------------------
    if (bid < KSLICES * BATCH) {
        red[sub][d] = acc;
        __syncthreads();
        if (sub == 0) {
            const int ks = bid & (KSLICES - 1);
            const int b  = bid >> 3;
            g_Vpart[(ks * BATCH + b) * HEAD_DIM + d] =
                red[0][d] + red[1][d] + red[2][d] + red[3][d];
        }
    }
    __syncthreads();
    if (t == 0) { __threadfence(); atomicAdd(&g_cnt1, 1); }

    // ---- Gate (128 CTAs, one per SM -> cannot deadlock) ------------------
    if (t == 0) {
        volatile int* p = &g_cnt1;
        while (*p < NPROLOG) __nanosleep(64);
        __threadfence();
    }
    __syncthreads();

    // ---- Phase 2: fold V partials, FMA against smem Wo -------------------
    {
        #pragma unroll
        for (int e = t; e < BATCH * HEAD_DIM; e += 256) {   // 2 entries/thread
            const int d2 = e & (HEAD_DIM - 1);
            float s = bv[d2];
            #pragma unroll
            for (int kk = 0; kk < KSLICES; ++kk)
                s += g_Vpart[kk * BATCH * HEAD_DIM + e];
            sV[e] = s;
        }
        // Own cp.async slots only (swo[ii*256+t] written & read by thread t).
        asm volatile("cp.async.wait_group 0;" ::: "memory");
        __syncthreads();

        float accb[BATCH];
        #pragma unroll
        for (int b2 = 0; b2 < BATCH; ++b2) accb[b2] = 0.f;

        #pragma unroll
        for (int ii = 0; ii < WO_PER_THREAD; ++ii) {
            const float w = swo[ii * 256 + t];          // conflict-free LDS
            const float* vv = sV + ii0 + ii;
            #pragma unroll
            for (int b2 = 0; b2 < BATCH; ++b2)
                accb[b2] += vv[b2 * HEAD_DIM] * w;      // smem broadcast
        }
        #pragma unroll
        for (int b2 = 0; b2 < BATCH; ++b2)
            atomicAdd(&g_row[b2 * D_MODEL + j], accb[b2]);
    }

    // ---- Release broadcast once this CTA's g_row writes are visible ------
    __threadfence();
    asm volatile("griddepcontrol.launch_dependents;" ::: "memory");

    // ---- Counter reset for next replay (last arriver) --------------------
    __syncthreads();
    if (t == 0) {
        if (atomicAdd(&g_cnt2, 1) == NPROLOG - 1) {
            g_cnt1 = 0;
            __threadfence();
            g_cnt2 = 0;
        }
    }
}

// ---------------------------------------------------------------------------
// Kernel 2: out[b,s,:] = row[b,:]. 134 MB of float4 stores; measured at the
// store-path wall (~6 TB/s effective -> ~21-22 us floor). PDL-launched so its
// 1024-CTA ramp overlaps the prologue.
// ---------------------------------------------------------------------------
#define S_PER_BLOCK 32
#define ROW_VEC4    (D_MODEL / 4)   // 256

__global__ __launch_bounds__(256, 8)
void broadcast_kernel(float4* __restrict__ out) {
    const int b  = blockIdx.y;
    const int s0 = blockIdx.x * S_PER_BLOCK;
    const int t  = threadIdx.x;

    // Block until the prologue grid has made g_row visible.
    asm volatile("griddepcontrol.wait;" ::: "memory");

    const float4 v = reinterpret_cast<const float4*>(g_row)[b * ROW_VEC4 + t];

    size_t base = ((size_t)b * SEQ + s0) * ROW_VEC4 + t;
    #pragma unroll
    for (int s = 0; s < S_PER_BLOCK; ++s) {
        out[base + (size_t)s * ROW_VEC4] = v;
    }
}

// ---------------------------------------------------------------------------
// Inputs (metadata order): 0 query, 1 key, 2 value, 3 Wq, 4 bq,
//                          5 Wk, 6 bk, 7 Wv, 8 bv, 9 Wo, 10 bo
// softmax over kv_len=1 is identically 1 -> query/key/Wq/bq/Wk/bk are dead.
// ---------------------------------------------------------------------------
extern "C" void kernel_launch(void* const* d_in, const int* in_sizes, int n_in,
                              void* d_out, int out_size) {
    const float* value = (const float*)d_in[2];
    const float* Wv    = (const float*)d_in[7];
    const float* bv    = (const float*)d_in[8];
    const float* Wo    = (const float*)d_in[9];
    const float* bo    = (const float*)d_in[10];
    float* out = (float*)d_out;

    prologue_fused_kernel<<<NPROLOG, 256>>>(value, Wv, bv, Wo, bo);

    // Broadcast launched as a programmatic dependent: spins up during the
    // prologue, blocks at griddepcontrol.wait until g_row is ready.
    cudaLaunchConfig_t cfg = {};
    cfg.gridDim  = dim3(SEQ / S_PER_BLOCK, BATCH);
    cfg.blockDim = dim3(256);
    cfg.stream   = 0;
    cudaLaunchAttribute attr[1];
    attr[0].id = cudaLaunchAttributeProgrammaticStreamSerialization;
    attr[0].val.programmaticStreamSerializationAllowed = 1;
    cfg.attrs = attr;
    cfg.numAttrs = 1;
    float4* out4 = (float4*)out;
    cudaLaunchKernelEx(&cfg, broadcast_kernel, out4);
}